// round 12
// baseline (speedup 1.0000x reference)
#include <cuda_runtime.h>
#include <cuda_fp16.h>

#define AA 16      // agents
#define EE 128     // embed dim
#define EPH 136    // f16 elems per smem row (272B, staggered for ldmatrix)
#define EPB 272    // row bytes
#define NB 4       // batches per CTA
#define SBUF (AA * EPB)                       // 4352 B per batch tile
#define SMEM_TOTAL (4 * NB * SBUF + NB * AA * 8)
#define THREADS 256
#define NEGV (-1e9f)

// Packed f16 weights: [m 8][nt 16][kk2 4][lane 32] uint4.
// .x={W[kb][n],W[kb+1][n]} .y={W[kb+8],W[kb+9]} .z={W[kb+16],W[kb+17]} .w={W[kb+24],W[kb+25]}
// where kb = kk2*32 + 2*(l&3), n = nt*8 + (l>>2).
__device__ uint4 g_wpack[8 * 16 * 4 * 32];

__device__ __forceinline__ unsigned pk2h(float lo, float hi) {
    unsigned r;
    asm("cvt.rn.f16x2.f32 %0, %1, %2;" : "=r"(r) : "f"(hi), "f"(lo));
    return r;
}
__device__ __forceinline__ float2 up2h(unsigned u) {
    const __half2 h = *reinterpret_cast<const __half2*>(&u);
    return __half22float2(h);
}
__device__ __forceinline__ unsigned hadd2u(unsigned a, unsigned b) {
    unsigned r;
    asm("add.f16x2 %0, %1, %2;" : "=r"(r) : "r"(a), "r"(b));
    return r;
}
__device__ __forceinline__ unsigned hmax2u(unsigned a, unsigned b) {
    unsigned r;
    asm("max.f16x2 %0, %1, %2;" : "=r"(r) : "r"(a), "r"(b));
    return r;
}
__device__ __forceinline__ float tanh_fast(float x) {
    float r;
    asm("tanh.approx.f32 %0, %1;" : "=f"(r) : "f"(x));
    return r;
}
__device__ __forceinline__ unsigned scvt(const void* p) {
    return (unsigned)__cvta_generic_to_shared(p);
}
__device__ __forceinline__ void ldsm4(unsigned& r0, unsigned& r1, unsigned& r2, unsigned& r3,
                                      unsigned a) {
    asm volatile("ldmatrix.sync.aligned.m8n8.x4.shared.b16 {%0,%1,%2,%3}, [%4];"
                 : "=r"(r0), "=r"(r1), "=r"(r2), "=r"(r3) : "r"(a));
}
__device__ __forceinline__ void ldsm4t(unsigned& r0, unsigned& r1, unsigned& r2, unsigned& r3,
                                       unsigned a) {
    asm volatile("ldmatrix.sync.aligned.m8n8.x4.trans.shared.b16 {%0,%1,%2,%3}, [%4];"
                 : "=r"(r0), "=r"(r1), "=r"(r2), "=r"(r3) : "r"(a));
}
__device__ __forceinline__ void ldsm2(unsigned& r0, unsigned& r1, unsigned a) {
    asm volatile("ldmatrix.sync.aligned.m8n8.x2.shared.b16 {%0,%1}, [%2];"
                 : "=r"(r0), "=r"(r1) : "r"(a));
}
// f16 in, f16 acc — D/C are 2 packed regs already in store layout
__device__ __forceinline__ void mmah(unsigned d[2], unsigned a0, unsigned a1, unsigned a2,
                                     unsigned a3, unsigned b0, unsigned b1) {
    asm("mma.sync.aligned.m16n8k16.row.col.f16.f16.f16.f16 "
        "{%0,%1}, {%2,%3,%4,%5}, {%6,%7}, {%0,%1};"
        : "+r"(d[0]), "+r"(d[1])
        : "r"(a0), "r"(a1), "r"(a2), "r"(a3), "r"(b0), "r"(b1));
}
// f16 in, f32 acc (attention + logits)
__device__ __forceinline__ void mmaf(float d[4], unsigned a0, unsigned a1, unsigned a2,
                                     unsigned a3, unsigned b0, unsigned b1) {
    asm("mma.sync.aligned.m16n8k16.row.col.f32.f16.f16.f32 "
        "{%0,%1,%2,%3}, {%4,%5,%6,%7}, {%8,%9}, {%0,%1,%2,%3};"
        : "+f"(d[0]), "+f"(d[1]), "+f"(d[2]), "+f"(d[3])
        : "r"(a0), "r"(a1), "r"(a2), "r"(a3), "r"(b0), "r"(b1));
}

// ---- prepass: repack 8 fp32 [128][128] weights into f16 uint4 fragment order ----
__global__ void __launch_bounds__(128) pack_weights_kernel(
    const float* __restrict__ Wq, const float* __restrict__ Wk,
    const float* __restrict__ Wv, const float* __restrict__ Wo,
    const float* __restrict__ W1, const float* __restrict__ W2,
    const float* __restrict__ Wqs, const float* __restrict__ Wks)
{
    const int idx = blockIdx.x * blockDim.x + threadIdx.x;   // 0..16383
    const int l  = idx & 31;
    const int k2 = (idx >> 5) & 3;
    const int nt = (idx >> 7) & 15;
    const int m  = idx >> 11;
    const float* W; float sc = 1.f;
    switch (m) {
        case 0: W = Wq; sc = 0.25f; break;                    // fold 1/sqrt(dh)
        case 1: W = Wk; break;
        case 2: W = Wv; break;
        case 3: W = Wo; break;
        case 4: W = W1; break;
        case 5: W = W2; break;
        case 6: W = Wqs; sc = 0.08838834764831845f; break;    // fold 1/sqrt(E)
        default: W = Wks; break;
    }
    const int n  = nt * 8 + (l >> 2);
    const int kb = k2 * 32 + 2 * (l & 3);
    uint4 o;
    o.x = pk2h(W[(kb +  0) * EE + n] * sc, W[(kb +  1) * EE + n] * sc);
    o.y = pk2h(W[(kb +  8) * EE + n] * sc, W[(kb +  9) * EE + n] * sc);
    o.z = pk2h(W[(kb + 16) * EE + n] * sc, W[(kb + 17) * EE + n] * sc);
    o.w = pk2h(W[(kb + 24) * EE + n] * sc, W[(kb + 25) * EE + n] * sc);
    g_wpack[idx] = o;
}

enum { MRAW = 0, MRES = 1, MBRELU = 2, MBRES = 3 };

// acc[nb][nt][2] (packed f16x2) = X[nb] @ W for this warp's 16 cols (2 ntiles).
// Weight fragments loaded ONCE per k2, reused across all 4 batches.
__device__ __forceinline__ void mm_acc(
    const unsigned char* X, const uint4* __restrict__ Wp,
    int w, int l, unsigned offA, unsigned acc[NB][2][2])
{
#pragma unroll
    for (int nb = 0; nb < NB; nb++) {
        acc[nb][0][0] = 0u; acc[nb][0][1] = 0u; acc[nb][1][0] = 0u; acc[nb][1][1] = 0u;
    }
    const unsigned xb0 = scvt(X) + offA;
#pragma unroll
    for (int k2 = 0; k2 < 4; k2++) {
        uint4 wfr[2];
#pragma unroll
        for (int nt = 0; nt < 2; nt++)
            wfr[nt] = __ldg(&Wp[(((w * 2 + nt) * 4) + k2) * 32 + l]);
#pragma unroll
        for (int nb = 0; nb < NB; nb++) {
            const unsigned xb = xb0 + nb * SBUF;
            unsigned a0, a1, a2, a3, c0, c1, c2, c3;
            ldsm4(a0, a1, a2, a3, xb + (2 * k2) * 32);
            ldsm4(c0, c1, c2, c3, xb + (2 * k2 + 1) * 32);
#pragma unroll
            for (int nt = 0; nt < 2; nt++) {
                mmah(acc[nb][nt], a0, a1, a2, a3, wfr[nt].x, wfr[nt].y);
                mmah(acc[nb][nt], c0, c1, c2, c3, wfr[nt].z, wfr[nt].w);
            }
        }
    }
}

// Full GEMM phase with packed-f16 smem epilogue.
template<int MODE>
__device__ __forceinline__ void mm_phase(
    const unsigned char* X, unsigned char* Y, const unsigned char* R,
    const float* __restrict__ bias,
    const uint4* __restrict__ Wp, int w, int l, unsigned offA, int r0, int cq)
{
    unsigned acc[NB][2][2];
    mm_acc(X, Wp, w, l, offA, acc);
#pragma unroll
    for (int nb = 0; nb < NB; nb++) {
        unsigned char* yb = Y + nb * SBUF;
        const unsigned char* rb = (MODE == MRES || MODE == MBRES) ? (R + nb * SBUF) : nullptr;
#pragma unroll
        for (int nt = 0; nt < 2; nt++) {
            const int colb = (w * 2 + nt) * 8 + cq;
            const unsigned off0 = r0 * EPB + colb * 2;
            const unsigned off1 = off0 + 8 * EPB;
            unsigned y0 = acc[nb][nt][0], y1 = acc[nb][nt][1];
            if (MODE == MRES) {
                y0 = hadd2u(y0, *(const unsigned*)(rb + off0));
                y1 = hadd2u(y1, *(const unsigned*)(rb + off1));
            } else if (MODE == MBRELU) {
                const float2 bv = *reinterpret_cast<const float2*>(&bias[colb]);
                const unsigned bh = pk2h(bv.x, bv.y);
                y0 = hmax2u(hadd2u(y0, bh), 0u);
                y1 = hmax2u(hadd2u(y1, bh), 0u);
            } else if (MODE == MBRES) {
                const float2 bv = *reinterpret_cast<const float2*>(&bias[colb]);
                const unsigned bh = pk2h(bv.x, bv.y);
                y0 = hadd2u(hadd2u(y0, bh), *(const unsigned*)(rb + off0));
                y1 = hadd2u(hadd2u(y1, bh), *(const unsigned*)(rb + off1));
            }
            *(unsigned*)(yb + off0) = y0;
            *(unsigned*)(yb + off1) = y1;
        }
    }
}

// In-place LN (fp32 math) on one batch tile; warp handles 8 rows.
__device__ __forceinline__ void ln_phase(unsigned char* Xb, const float* __restrict__ g,
                                         const float* __restrict__ bsh, int hv, int l)
{
    const float4 g4 = *reinterpret_cast<const float4*>(&g[l * 4]);
    const float4 b4 = *reinterpret_cast<const float4*>(&bsh[l * 4]);
#pragma unroll
    for (int rr = 0; rr < 8; rr++) {
        const int r = hv * 8 + rr;
        unsigned char* rp = Xb + r * EPB + 8 * l;
        const uint2 p = *(const uint2*)rp;
        const float2 lo = up2h(p.x), hi = up2h(p.y);
        float s  = lo.x + lo.y + hi.x + hi.y;
        float ss = fmaf(lo.x, lo.x, fmaf(lo.y, lo.y, fmaf(hi.x, hi.x, hi.y * hi.y)));
#pragma unroll
        for (int o = 16; o > 0; o >>= 1) {
            s  += __shfl_xor_sync(0xffffffffu, s, o);
            ss += __shfl_xor_sync(0xffffffffu, ss, o);
        }
        const float mu  = s * (1.f / 128.f);
        const float var = ss * (1.f / 128.f) - mu * mu;
        const float inv = rsqrtf(var + 1e-5f);
        uint2 q;
        q.x = pk2h((lo.x - mu) * inv * g4.x + b4.x, (lo.y - mu) * inv * g4.y + b4.y);
        q.y = pk2h((hi.x - mu) * inv * g4.z + b4.z, (hi.y - mu) * inv * g4.w + b4.w);
        *(uint2*)rp = q;
    }
}

__global__ void __launch_bounds__(THREADS, 3)
conflict_model_kernel(
    const float* __restrict__ agent_embed,  // [B,16,128]
    const float* __restrict__ city_embed,   // [B,128,128]
    const int*   __restrict__ acts,         // [B,16]
    const float* __restrict__ ln1_g, const float* __restrict__ ln1_b,
    const float* __restrict__ b1v,  const float* __restrict__ b2v,
    const float* __restrict__ ln2_g, const float* __restrict__ ln2_b,
    float* __restrict__ out)                // [B,16,16]
{
    extern __shared__ __align__(16) unsigned char smem[];
    unsigned char* sA = smem;                 // agent (live to the end: ks src)
    unsigned char* sX = smem + 1 * NB * SBUF; // selected -> cac2 (LN2)
    unsigned char* sV = smem + 2 * NB * SBUF; // v -> h(postLN1) -> ks
    unsigned char* sW = smem + 3 * NB * SBUF; // attnO -> ffn hidden -> qs
    int*      s_acts = (int*)(smem + 4 * NB * SBUF);
    unsigned* s_mask = (unsigned*)(s_acts + NB * AA);

    const int t = threadIdx.x;
    const int w = t >> 5, l = t & 31;       // 8 warps; warp = 16 cols = head w
    const int hv = w & 1, nbw = w >> 1;
    const int r0 = l >> 2, cq = 2 * (l & 3);
    const int b0 = blockIdx.x * NB;

    const unsigned offA = (unsigned)(((l & 7) + ((l >> 3) & 1) * 8) * EPB + ((l >> 4) & 1) * 16);

    // ---- acts + mask (even warps) & agent rows (all warps) ----
    if (hv == 0) {
        int av = (l < AA) ? acts[(b0 + nbw) * AA + l] : 0;
        unsigned m = 0;
#pragma unroll
        for (int j = 0; j < AA; j++) {
            const int aj = __shfl_sync(0xffffffffu, av, j);
            const bool conflict = (av == 0) ? (j == l) : (aj == av);
            if (!conflict) m |= (1u << j);
        }
        if (l < AA) { s_acts[nbw * AA + l] = av; s_mask[nbw * AA + l] = m; }
    }
#pragma unroll
    for (int rr = 0; rr < 8; rr++) {
        const int r = hv * 8 + rr;
        const float4 v = *reinterpret_cast<const float4*>(
            agent_embed + ((size_t)(b0 + nbw) * AA + r) * EE + 4 * l);
        uint2 p; p.x = pk2h(v.x, v.y); p.y = pk2h(v.z, v.w);
        *(uint2*)(sA + nbw * SBUF + r * EPB + 8 * l) = p;
    }
    __syncthreads();
#pragma unroll
    for (int rr = 0; rr < 8; rr++) {
        const int r = hv * 8 + rr;
        const int ci = s_acts[nbw * AA + r];
        const float4 v = *reinterpret_cast<const float4*>(
            city_embed + ((size_t)(b0 + nbw) * 128 + ci) * EE + 4 * l);
        uint2 p; p.x = pk2h(v.x, v.y); p.y = pk2h(v.z, v.w);
        *(uint2*)(sX + nbw * SBUF + r * EPB + 8 * l) = p;
    }
    __syncthreads();

    // ---- v -> smem ; k, q -> packed register fragments ----
    mm_phase<MRAW>(sA, sV, nullptr, nullptr, g_wpack + 2 * 2048, w, l, offA, r0, cq);
    unsigned kp[NB][2][2], qp[NB][2][2];
    mm_acc(sA, g_wpack + 1 * 2048, w, l, offA, kp);
    mm_acc(sX, g_wpack + 0 * 2048, w, l, offA, qp);  // Wq pre-scaled by 0.25
    __syncwarp();  // V cols 16w are warp-private: STS -> ldsm ordering only

    // ---- attention: warp w = head w, all 4 batches ----
#pragma unroll
    for (int nb = 0; nb < NB; nb++) {
        const unsigned vb = scvt(sV + nb * SBUF);
        const unsigned m0 = s_mask[nb * AA + r0], m1 = s_mask[nb * AA + r0 + 8];
        const unsigned cb = 32u * w;  // byte offset of this head's 16 cols
        const unsigned a0 = qp[nb][0][0], a1 = qp[nb][0][1];
        const unsigned a2 = qp[nb][1][0], a3 = qp[nb][1][1];
        float s0[4] = {0, 0, 0, 0}, s1[4] = {0, 0, 0, 0};
        mmaf(s0, a0, a1, a2, a3, kp[nb][0][0], kp[nb][1][0]);
        mmaf(s1, a0, a1, a2, a3, kp[nb][0][1], kp[nb][1][1]);
        if ((m0 >> cq) & 1)       s0[0] = NEGV;
        if ((m0 >> (cq + 1)) & 1) s0[1] = NEGV;
        if ((m1 >> cq) & 1)       s0[2] = NEGV;
        if ((m1 >> (cq + 1)) & 1) s0[3] = NEGV;
        if ((m0 >> (cq + 8)) & 1) s1[0] = NEGV;
        if ((m0 >> (cq + 9)) & 1) s1[1] = NEGV;
        if ((m1 >> (cq + 8)) & 1) s1[2] = NEGV;
        if ((m1 >> (cq + 9)) & 1) s1[3] = NEGV;
        float mx0 = fmaxf(fmaxf(s0[0], s0[1]), fmaxf(s1[0], s1[1]));
        float mx1 = fmaxf(fmaxf(s0[2], s0[3]), fmaxf(s1[2], s1[3]));
        mx0 = fmaxf(mx0, __shfl_xor_sync(0xffffffffu, mx0, 1));
        mx0 = fmaxf(mx0, __shfl_xor_sync(0xffffffffu, mx0, 2));
        mx1 = fmaxf(mx1, __shfl_xor_sync(0xffffffffu, mx1, 1));
        mx1 = fmaxf(mx1, __shfl_xor_sync(0xffffffffu, mx1, 2));
        s0[0] = __expf(s0[0] - mx0); s0[1] = __expf(s0[1] - mx0);
        s1[0] = __expf(s1[0] - mx0); s1[1] = __expf(s1[1] - mx0);
        s0[2] = __expf(s0[2] - mx1); s0[3] = __expf(s0[3] - mx1);
        s1[2] = __expf(s1[2] - mx1); s1[3] = __expf(s1[3] - mx1);
        float sm0 = s0[0] + s0[1] + s1[0] + s1[1];
        float sm1 = s0[2] + s0[3] + s1[2] + s1[3];
        sm0 += __shfl_xor_sync(0xffffffffu, sm0, 1);
        sm0 += __shfl_xor_sync(0xffffffffu, sm0, 2);
        sm1 += __shfl_xor_sync(0xffffffffu, sm1, 1);
        sm1 += __shfl_xor_sync(0xffffffffu, sm1, 2);
        const float inv0 = 1.f / sm0, inv1 = 1.f / sm1;
        const unsigned p0 = pk2h(s0[0], s0[1]);
        const unsigned p1 = pk2h(s0[2], s0[3]);
        const unsigned p2 = pk2h(s1[0], s1[1]);
        const unsigned p3 = pk2h(s1[2], s1[3]);
        unsigned v0, v1, v2, v3;
        ldsm4t(v0, v1, v2, v3, vb + offA + cb);
        float o0[4] = {0, 0, 0, 0}, o1[4] = {0, 0, 0, 0};
        mmaf(o0, p0, p1, p2, p3, v0, v1);
        mmaf(o1, p0, p1, p2, p3, v2, v3);
        unsigned char* yb = sW + nb * SBUF;
        const unsigned c0 = r0 * EPB + (16 * w + cq) * 2;
        const unsigned c1 = c0 + 8 * EPB;
        *(unsigned*)(yb + c0)      = pk2h(o0[0] * inv0, o0[1] * inv0);
        *(unsigned*)(yb + c1)      = pk2h(o0[2] * inv1, o0[3] * inv1);
        *(unsigned*)(yb + c0 + 16) = pk2h(o1[0] * inv0, o1[1] * inv0);
        *(unsigned*)(yb + c1 + 16) = pk2h(o1[2] * inv1, o1[3] * inv1);
    }
    __syncthreads();

    // ---- attnO @ Wo + selected -> sV (v dead); LN1 ----
    mm_phase<MRES>(sW, sV, sX, nullptr, g_wpack + 3 * 2048, w, l, offA, r0, cq);
    __syncthreads();
    ln_phase(sV + nbw * SBUF, ln1_g, ln1_b, hv, l);
    __syncthreads();

    // ---- FFN hidden = relu(h @ W1 + b1) -> sW (attnO dead) ----
    mm_phase<MBRELU>(sV, sW, nullptr, b1v, g_wpack + 4 * 2048, w, l, offA, r0, cq);
    __syncthreads();

    // ---- FFN out + b2 + h -> sX (selected dead); LN2 ----
    mm_phase<MBRES>(sW, sX, sV, b2v, g_wpack + 5 * 2048, w, l, offA, r0, cq);
    __syncthreads();
    ln_phase(sX + nbw * SBUF, ln2_g, ln2_b, hv, l);
    __syncthreads();

    // ---- qs = cac2 @ Wq_s(pre-scaled) -> sW ; ks = agent @ Wk_s -> sV ----
    mm_phase<MRAW>(sX, sW, nullptr, nullptr, g_wpack + 6 * 2048, w, l, offA, r0, cq);
    mm_phase<MRAW>(sA, sV, nullptr, nullptr, g_wpack + 7 * 2048, w, l, offA, r0, cq);
    __syncthreads();

    // ---- logits (f32 acc): warp = (batch nbw, n-tile hv) ----
    {
        const unsigned qb = scvt(sW + nbw * SBUF);
        const unsigned kb = scvt(sV + nbw * SBUF) + hv * 8 * EPB;
        const unsigned offB2 = (unsigned)((l & 7) * EPB + ((l >> 3) & 1) * 16);
        float d[4] = {0, 0, 0, 0};
#pragma unroll
        for (int kk = 0; kk < 8; kk++) {
            unsigned a0, a1, a2, a3, bb0, bb1;
            ldsm4(a0, a1, a2, a3, qb + offA + kk * 32);
            ldsm2(bb0, bb1, kb + offB2 + kk * 32);
            mmaf(d, a0, a1, a2, a3, bb0, bb1);
        }
        const int colb = hv * 8 + cq;
        const unsigned m0 = s_mask[nbw * AA + r0], m1 = s_mask[nbw * AA + r0 + 8];
        const float o0 = ((m0 >> colb) & 1u)       ? NEGV : 10.f * tanh_fast(d[0]);
        const float o1 = ((m0 >> (colb + 1)) & 1u) ? NEGV : 10.f * tanh_fast(d[1]);
        const float o2 = ((m1 >> colb) & 1u)       ? NEGV : 10.f * tanh_fast(d[2]);
        const float o3 = ((m1 >> (colb + 1)) & 1u) ? NEGV : 10.f * tanh_fast(d[3]);
        float* ob = out + (size_t)(b0 + nbw) * (AA * AA);
        *reinterpret_cast<float2*>(&ob[r0 * AA + colb])       = make_float2(o0, o1);
        *reinterpret_cast<float2*>(&ob[(r0 + 8) * AA + colb]) = make_float2(o2, o3);
    }
}

extern "C" void kernel_launch(void* const* d_in, const int* in_sizes, int n_in,
                              void* d_out, int out_size) {
    const float* agent_embed = (const float*)d_in[0];
    const float* city_embed  = (const float*)d_in[1];
    const int*   acts        = (const int*)d_in[2];
    const float* Wq    = (const float*)d_in[3];
    const float* Wk    = (const float*)d_in[4];
    const float* Wv    = (const float*)d_in[5];
    const float* Wo    = (const float*)d_in[6];
    const float* ln1_g = (const float*)d_in[7];
    const float* ln1_b = (const float*)d_in[8];
    const float* W1    = (const float*)d_in[9];
    const float* b1v   = (const float*)d_in[10];
    const float* W2    = (const float*)d_in[11];
    const float* b2v   = (const float*)d_in[12];
    const float* ln2_g = (const float*)d_in[13];
    const float* ln2_b = (const float*)d_in[14];
    const float* Wqs   = (const float*)d_in[15];
    const float* Wks   = (const float*)d_in[16];

    const int B = in_sizes[0] / (AA * EE);

    // Opt-in to >48KB dynamic smem (idempotent; not a stream op, capture-safe).
    cudaFuncSetAttribute(conflict_model_kernel,
                         cudaFuncAttributeMaxDynamicSharedMemorySize, SMEM_TOTAL);

    pack_weights_kernel<<<128, 128>>>(Wq, Wk, Wv, Wo, W1, W2, Wqs, Wks);
    conflict_model_kernel<<<B / NB, THREADS, SMEM_TOTAL>>>(
        agent_embed, city_embed, acts,
        ln1_g, ln1_b, b1v, b2v, ln2_g, ln2_b,
        (float*)d_out);
}

// round 14
// speedup vs baseline: 1.0675x; 1.0675x over previous
#include <cuda_runtime.h>
#include <cuda_fp16.h>

#define AA 16      // agents
#define EE 128     // embed dim
#define EPH 136    // f16 elems per smem row (272B, staggered for ldmatrix)
#define EPB 272    // row bytes
#define NB 2       // batches per CTA
#define NEGV (-1e9f)

// Packed f16 weights: [m 8][nt 16][kk2 4][lane 32] uint4.
__device__ uint4 g_wpack[8 * 16 * 4 * 32];

__device__ __forceinline__ unsigned pk2h(float lo, float hi) {
    unsigned r;
    asm("cvt.rn.f16x2.f32 %0, %1, %2;" : "=r"(r) : "f"(hi), "f"(lo));
    return r;
}
__device__ __forceinline__ float2 up2h(unsigned u) {
    const __half2 h = *reinterpret_cast<const __half2*>(&u);
    return __half22float2(h);
}
__device__ __forceinline__ unsigned hadd2u(unsigned a, unsigned b) {
    unsigned r;
    asm("add.f16x2 %0, %1, %2;" : "=r"(r) : "r"(a), "r"(b));
    return r;
}
__device__ __forceinline__ unsigned hmax2u(unsigned a, unsigned b) {
    unsigned r;
    asm("max.f16x2 %0, %1, %2;" : "=r"(r) : "r"(a), "r"(b));
    return r;
}
__device__ __forceinline__ float tanh_fast(float x) {
    float r;
    asm("tanh.approx.f32 %0, %1;" : "=f"(r) : "f"(x));
    return r;
}
__device__ __forceinline__ unsigned scvt(const void* p) {
    return (unsigned)__cvta_generic_to_shared(p);
}
__device__ __forceinline__ void ldsm4(unsigned& r0, unsigned& r1, unsigned& r2, unsigned& r3,
                                      unsigned a) {
    asm volatile("ldmatrix.sync.aligned.m8n8.x4.shared.b16 {%0,%1,%2,%3}, [%4];"
                 : "=r"(r0), "=r"(r1), "=r"(r2), "=r"(r3) : "r"(a));
}
__device__ __forceinline__ void ldsm4t(unsigned& r0, unsigned& r1, unsigned& r2, unsigned& r3,
                                       unsigned a) {
    asm volatile("ldmatrix.sync.aligned.m8n8.x4.trans.shared.b16 {%0,%1,%2,%3}, [%4];"
                 : "=r"(r0), "=r"(r1), "=r"(r2), "=r"(r3) : "r"(a));
}
// f16 in, f16 acc — D/C are 2 packed regs already in store layout
__device__ __forceinline__ void mmah(unsigned d[2], unsigned a0, unsigned a1, unsigned a2,
                                     unsigned a3, unsigned b0, unsigned b1) {
    asm("mma.sync.aligned.m16n8k16.row.col.f16.f16.f16.f16 "
        "{%0,%1}, {%2,%3,%4,%5}, {%6,%7}, {%0,%1};"
        : "+r"(d[0]), "+r"(d[1])
        : "r"(a0), "r"(a1), "r"(a2), "r"(a3), "r"(b0), "r"(b1));
}
// f16 in, f32 acc (attention + logits)
__device__ __forceinline__ void mmaf(float d[4], unsigned a0, unsigned a1, unsigned a2,
                                     unsigned a3, unsigned b0, unsigned b1) {
    asm("mma.sync.aligned.m16n8k16.row.col.f32.f16.f16.f32 "
        "{%0,%1,%2,%3}, {%4,%5,%6,%7}, {%8,%9}, {%0,%1,%2,%3};"
        : "+f"(d[0]), "+f"(d[1]), "+f"(d[2]), "+f"(d[3])
        : "r"(a0), "r"(a1), "r"(a2), "r"(a3), "r"(b0), "r"(b1));
}

// ---- prepass: repack 8 fp32 [128][128] weights into f16 uint4 fragment order ----
__global__ void __launch_bounds__(128) pack_weights_kernel(
    const float* __restrict__ Wq, const float* __restrict__ Wk,
    const float* __restrict__ Wv, const float* __restrict__ Wo,
    const float* __restrict__ W1, const float* __restrict__ W2,
    const float* __restrict__ Wqs, const float* __restrict__ Wks)
{
    const int idx = blockIdx.x * blockDim.x + threadIdx.x;   // 0..16383
    const int l  = idx & 31;
    const int k2 = (idx >> 5) & 3;
    const int nt = (idx >> 7) & 15;
    const int m  = idx >> 11;
    const float* W; float sc = 1.f;
    switch (m) {
        case 0: W = Wq; sc = 0.25f; break;                    // fold 1/sqrt(dh)
        case 1: W = Wk; break;
        case 2: W = Wv; break;
        case 3: W = Wo; break;
        case 4: W = W1; break;
        case 5: W = W2; break;
        case 6: W = Wqs; sc = 0.08838834764831845f; break;    // fold 1/sqrt(E)
        default: W = Wks; break;
    }
    const int n  = nt * 8 + (l >> 2);
    const int kb = k2 * 32 + 2 * (l & 3);
    uint4 o;
    o.x = pk2h(W[(kb +  0) * EE + n] * sc, W[(kb +  1) * EE + n] * sc);
    o.y = pk2h(W[(kb +  8) * EE + n] * sc, W[(kb +  9) * EE + n] * sc);
    o.z = pk2h(W[(kb + 16) * EE + n] * sc, W[(kb + 17) * EE + n] * sc);
    o.w = pk2h(W[(kb + 24) * EE + n] * sc, W[(kb + 25) * EE + n] * sc);
    g_wpack[idx] = o;
}

enum { MRAW = 0, MRES = 1, MBRELU = 2, MBRES = 3 };

// acc[nb][nt][2] (packed f16x2 pairs) = X[nb] @ W for this warp's 32 cols.
__device__ __forceinline__ void mm_acc(
    const __half (*Xs)[AA][EPH], const uint4* __restrict__ Wp,
    int w, int l, unsigned offA, unsigned acc[NB][4][2])
{
#pragma unroll
    for (int nb = 0; nb < NB; nb++)
#pragma unroll
        for (int nt = 0; nt < 4; nt++) { acc[nb][nt][0] = 0u; acc[nb][nt][1] = 0u; }
    const unsigned xb0 = scvt(&Xs[0][0][0]) + offA;
    const unsigned xb1 = scvt(&Xs[1][0][0]) + offA;
#pragma unroll
    for (int k2 = 0; k2 < 4; k2++) {
        uint4 wfr[4];
#pragma unroll
        for (int nt = 0; nt < 4; nt++)
            wfr[nt] = __ldg(&Wp[(((w * 4 + nt) * 4) + k2) * 32 + l]);
#pragma unroll
        for (int nb = 0; nb < NB; nb++) {
            const unsigned xb = nb ? xb1 : xb0;
            unsigned a0, a1, a2, a3, c0, c1, c2, c3;
            ldsm4(a0, a1, a2, a3, xb + (2 * k2) * 32);
            ldsm4(c0, c1, c2, c3, xb + (2 * k2 + 1) * 32);
#pragma unroll
            for (int nt = 0; nt < 4; nt++) {
                mmah(acc[nb][nt], a0, a1, a2, a3, wfr[nt].x, wfr[nt].y);
                mmah(acc[nb][nt], c0, c1, c2, c3, wfr[nt].z, wfr[nt].w);
            }
        }
    }
}

// Full GEMM phase with packed-f16 smem epilogue (no cvt anywhere).
template<int MODE>
__device__ __forceinline__ void mm_phase(
    const __half (*Xs)[AA][EPH], __half (*Ys)[AA][EPH],
    const __half (*Rs)[AA][EPH], const float* __restrict__ bias,
    const uint4* __restrict__ Wp, int w, int l, unsigned offA, int r0, int cq)
{
    unsigned acc[NB][4][2];
    mm_acc(Xs, Wp, w, l, offA, acc);
#pragma unroll
    for (int nb = 0; nb < NB; nb++) {
        char* yb = (char*)&Ys[nb][0][0];
        const char* rb = (MODE == MRES || MODE == MBRES) ? (const char*)&Rs[nb][0][0] : nullptr;
#pragma unroll
        for (int nt = 0; nt < 4; nt++) {
            const int colb = (w * 4 + nt) * 8 + cq;
            const unsigned off0 = r0 * EPB + colb * 2;
            const unsigned off1 = off0 + 8 * EPB;
            unsigned y0 = acc[nb][nt][0], y1 = acc[nb][nt][1];
            if (MODE == MRES) {
                y0 = hadd2u(y0, *(const unsigned*)(rb + off0));
                y1 = hadd2u(y1, *(const unsigned*)(rb + off1));
            } else if (MODE == MBRELU) {
                const float2 bv = *reinterpret_cast<const float2*>(&bias[colb]);
                const unsigned bh = pk2h(bv.x, bv.y);
                y0 = hmax2u(hadd2u(y0, bh), 0u);
                y1 = hmax2u(hadd2u(y1, bh), 0u);
            } else if (MODE == MBRES) {
                const float2 bv = *reinterpret_cast<const float2*>(&bias[colb]);
                const unsigned bh = pk2h(bv.x, bv.y);
                y0 = hadd2u(hadd2u(y0, bh), *(const unsigned*)(rb + off0));
                y1 = hadd2u(hadd2u(y1, bh), *(const unsigned*)(rb + off1));
            }
            *(unsigned*)(yb + off0) = y0;
            *(unsigned*)(yb + off1) = y1;
        }
    }
}

// In-place LN (fp32 math); warp handles 8 rows of batch (lane = fixed 4 cols).
__device__ __forceinline__ void ln_phase(__half (*X)[EPH], const float* __restrict__ g,
                                         const float* __restrict__ bsh, int hv, int l)
{
    const float4 g4 = *reinterpret_cast<const float4*>(&g[l * 4]);
    const float4 b4 = *reinterpret_cast<const float4*>(&bsh[l * 4]);
#pragma unroll
    for (int rr = 0; rr < 8; rr++) {
        const int r = hv * 8 + rr;
        char* rp = (char*)&X[r][0] + 8 * l;
        const uint2 p = *(const uint2*)rp;
        const float2 lo = up2h(p.x), hi = up2h(p.y);
        float s  = lo.x + lo.y + hi.x + hi.y;
        float ss = fmaf(lo.x, lo.x, fmaf(lo.y, lo.y, fmaf(hi.x, hi.x, hi.y * hi.y)));
#pragma unroll
        for (int o = 16; o > 0; o >>= 1) {
            s  += __shfl_xor_sync(0xffffffffu, s, o);
            ss += __shfl_xor_sync(0xffffffffu, ss, o);
        }
        const float mu  = s * (1.f / 128.f);
        const float var = ss * (1.f / 128.f) - mu * mu;
        const float inv = rsqrtf(var + 1e-5f);
        uint2 q;
        q.x = pk2h((lo.x - mu) * inv * g4.x + b4.x, (lo.y - mu) * inv * g4.y + b4.y);
        q.y = pk2h((hi.x - mu) * inv * g4.z + b4.z, (hi.y - mu) * inv * g4.w + b4.w);
        *(uint2*)rp = q;
    }
}

__global__ void __launch_bounds__(128, 6)
conflict_model_kernel(
    const float* __restrict__ agent_embed,  // [B,16,128]
    const float* __restrict__ city_embed,   // [B,128,128]
    const int*   __restrict__ acts,         // [B,16]
    const float* __restrict__ ln1_g, const float* __restrict__ ln1_b,
    const float* __restrict__ b1v,  const float* __restrict__ b2v,
    const float* __restrict__ ln2_g, const float* __restrict__ ln2_b,
    float* __restrict__ out)                // [B,16,16]
{
    __shared__ __align__(16) __half sA[NB][AA][EPH];   // agent (ks source)
    __shared__ __align__(16) __half sX[NB][AA][EPH];   // selected -> cac2 (LN2)
    __shared__ __align__(16) __half sV[NB][AA][EPH];   // v -> h -> logit partials nb0
    __shared__ __align__(16) __half sW[NB][AA][EPH];   // attnO -> ffn hid -> partials nb1
    __shared__ int      s_acts[NB][AA];
    __shared__ unsigned s_mask[NB][AA];

    const int t = threadIdx.x;
    const int w = t >> 5, l = t & 31;
    const int hv = w & 1, nbw = w >> 1;
    const int r0 = l >> 2, cq = 2 * (l & 3);
    const int b0 = blockIdx.x * NB;

    const unsigned offA = (unsigned)(((l & 7) + ((l >> 3) & 1) * 8) * EPB + ((l >> 4) & 1) * 16);

    // ---- acts + mask (warps 0,2) & agent rows (all warps) ----
    if (hv == 0) {
        int av = (l < AA) ? acts[(b0 + nbw) * AA + l] : 0;
        unsigned m = 0;
#pragma unroll
        for (int j = 0; j < AA; j++) {
            const int aj = __shfl_sync(0xffffffffu, av, j);
            const bool conflict = (av == 0) ? (j == l) : (aj == av);
            if (!conflict) m |= (1u << j);
        }
        if (l < AA) { s_acts[nbw][l] = av; s_mask[nbw][l] = m; }
    }
#pragma unroll
    for (int rr = 0; rr < 8; rr++) {
        const int r = hv * 8 + rr;
        const float4 v = *reinterpret_cast<const float4*>(
            agent_embed + ((size_t)(b0 + nbw) * AA + r) * EE + 4 * l);
        uint2 p; p.x = pk2h(v.x, v.y); p.y = pk2h(v.z, v.w);
        *(uint2*)((char*)&sA[nbw][r][0] + 8 * l) = p;
    }
    __syncthreads();
#pragma unroll
    for (int rr = 0; rr < 8; rr++) {
        const int r = hv * 8 + rr;
        const int ci = s_acts[nbw][r];
        const float4 v = *reinterpret_cast<const float4*>(
            city_embed + ((size_t)(b0 + nbw) * 128 + ci) * EE + 4 * l);
        uint2 p; p.x = pk2h(v.x, v.y); p.y = pk2h(v.z, v.w);
        *(uint2*)((char*)&sX[nbw][r][0] + 8 * l) = p;
    }
    __syncthreads();

    // ---- v -> smem ; k, q -> packed register fragments ----
    mm_phase<MRAW>(sA, sV, nullptr, nullptr, g_wpack + 2 * 2048, w, l, offA, r0, cq);
    unsigned kp[NB][4][2], qp[NB][4][2];
    mm_acc(sA, g_wpack + 1 * 2048, w, l, offA, kp);
    mm_acc(sX, g_wpack + 0 * 2048, w, l, offA, qp);  // Wq pre-scaled by 0.25
    __syncwarp();  // V tile (cols 32w) is warp-private

    // ---- attention: warp w handles heads 2w, 2w+1 for BOTH batches ----
#pragma unroll
    for (int nb = 0; nb < NB; nb++) {
        const unsigned vb = scvt(&sV[nb][0][0]);
        const unsigned m0 = s_mask[nb][r0], m1 = s_mask[nb][r0 + 8];
#pragma unroll
        for (int hh = 0; hh < 2; hh++) {
            const int h = 2 * w + hh;
            const unsigned cb = 32u * h;
            const unsigned a0 = qp[nb][2 * hh][0], a1 = qp[nb][2 * hh][1];
            const unsigned a2 = qp[nb][2 * hh + 1][0], a3 = qp[nb][2 * hh + 1][1];
            float s0[4] = {0, 0, 0, 0}, s1[4] = {0, 0, 0, 0};
            mmaf(s0, a0, a1, a2, a3, kp[nb][2 * hh][0], kp[nb][2 * hh + 1][0]);
            mmaf(s1, a0, a1, a2, a3, kp[nb][2 * hh][1], kp[nb][2 * hh + 1][1]);
            if ((m0 >> cq) & 1)       s0[0] = NEGV;
            if ((m0 >> (cq + 1)) & 1) s0[1] = NEGV;
            if ((m1 >> cq) & 1)       s0[2] = NEGV;
            if ((m1 >> (cq + 1)) & 1) s0[3] = NEGV;
            if ((m0 >> (cq + 8)) & 1) s1[0] = NEGV;
            if ((m0 >> (cq + 9)) & 1) s1[1] = NEGV;
            if ((m1 >> (cq + 8)) & 1) s1[2] = NEGV;
            if ((m1 >> (cq + 9)) & 1) s1[3] = NEGV;
            float mx0 = fmaxf(fmaxf(s0[0], s0[1]), fmaxf(s1[0], s1[1]));
            float mx1 = fmaxf(fmaxf(s0[2], s0[3]), fmaxf(s1[2], s1[3]));
            mx0 = fmaxf(mx0, __shfl_xor_sync(0xffffffffu, mx0, 1));
            mx0 = fmaxf(mx0, __shfl_xor_sync(0xffffffffu, mx0, 2));
            mx1 = fmaxf(mx1, __shfl_xor_sync(0xffffffffu, mx1, 1));
            mx1 = fmaxf(mx1, __shfl_xor_sync(0xffffffffu, mx1, 2));
            s0[0] = __expf(s0[0] - mx0); s0[1] = __expf(s0[1] - mx0);
            s1[0] = __expf(s1[0] - mx0); s1[1] = __expf(s1[1] - mx0);
            s0[2] = __expf(s0[2] - mx1); s0[3] = __expf(s0[3] - mx1);
            s1[2] = __expf(s1[2] - mx1); s1[3] = __expf(s1[3] - mx1);
            float sm0 = s0[0] + s0[1] + s1[0] + s1[1];
            float sm1 = s0[2] + s0[3] + s1[2] + s1[3];
            sm0 += __shfl_xor_sync(0xffffffffu, sm0, 1);
            sm0 += __shfl_xor_sync(0xffffffffu, sm0, 2);
            sm1 += __shfl_xor_sync(0xffffffffu, sm1, 1);
            sm1 += __shfl_xor_sync(0xffffffffu, sm1, 2);
            const float inv0 = 1.f / sm0, inv1 = 1.f / sm1;
            const unsigned p0 = pk2h(s0[0], s0[1]);
            const unsigned p1 = pk2h(s0[2], s0[3]);
            const unsigned p2 = pk2h(s1[0], s1[1]);
            const unsigned p3 = pk2h(s1[2], s1[3]);
            unsigned v0, v1, v2, v3;
            ldsm4t(v0, v1, v2, v3, vb + offA + cb);
            float o0[4] = {0, 0, 0, 0}, o1[4] = {0, 0, 0, 0};
            mmaf(o0, p0, p1, p2, p3, v0, v1);
            mmaf(o1, p0, p1, p2, p3, v2, v3);
            char* yb = (char*)&sW[nb][0][0];
            const unsigned c0 = r0 * EPB + (16 * h + cq) * 2;
            const unsigned c1 = c0 + 8 * EPB;
            *(unsigned*)(yb + c0)      = pk2h(o0[0] * inv0, o0[1] * inv0);
            *(unsigned*)(yb + c1)      = pk2h(o0[2] * inv1, o0[3] * inv1);
            *(unsigned*)(yb + c0 + 16) = pk2h(o1[0] * inv0, o1[1] * inv0);
            *(unsigned*)(yb + c1 + 16) = pk2h(o1[2] * inv1, o1[3] * inv1);
        }
    }
    __syncthreads();

    // ---- attnO @ Wo + selected -> sV (v dead); LN1 ----
    mm_phase<MRES>(sW, sV, sX, nullptr, g_wpack + 3 * 2048, w, l, offA, r0, cq);
    __syncthreads();
    ln_phase(sV[nbw], ln1_g, ln1_b, hv, l);
    __syncthreads();

    // ---- FFN hidden = relu(h @ W1 + b1) -> sW (attnO dead) ----
    mm_phase<MBRELU>(sV, sW, nullptr, b1v, g_wpack + 4 * 2048, w, l, offA, r0, cq);
    __syncthreads();

    // ---- FFN out + b2 + h -> sX (selected dead); LN2 ----
    mm_phase<MBRES>(sW, sX, sV, b2v, g_wpack + 5 * 2048, w, l, offA, r0, cq);
    __syncthreads();
    ln_phase(sX[nbw], ln2_g, ln2_b, hv, l);
    __syncthreads();

    // ---- qs, ks -> register fragments; per-warp partial logits over 32-col slice ----
    {
        unsigned qs2[NB][4][2], ks2[NB][4][2];
        mm_acc(sX, g_wpack + 6 * 2048, w, l, offA, qs2);  // Wq_s pre-scaled by 1/sqrt(E)
        mm_acc(sA, g_wpack + 7 * 2048, w, l, offA, ks2);
        // Partial logits: warp w's cols = E-slice [32w,32w+32). Row stride 20 floats.
#pragma unroll
        for (int nb = 0; nb < NB; nb++) {
            float d0[4] = {0, 0, 0, 0}, d1[4] = {0, 0, 0, 0};
#pragma unroll
            for (int j = 0; j < 2; j++) {
                const unsigned a0 = qs2[nb][2 * j][0], a1 = qs2[nb][2 * j][1];
                const unsigned a2 = qs2[nb][2 * j + 1][0], a3 = qs2[nb][2 * j + 1][1];
                mmaf(d0, a0, a1, a2, a3, ks2[nb][2 * j][0], ks2[nb][2 * j + 1][0]);
                mmaf(d1, a0, a1, a2, a3, ks2[nb][2 * j][1], ks2[nb][2 * j + 1][1]);
            }
            float* pw = (float*)(nb ? (void*)&sW[0][0][0] : (void*)&sV[0][0][0]) + w * 320;
            *(float2*)&pw[r0 * 20 + cq]            = make_float2(d0[0], d0[1]);
            *(float2*)&pw[(r0 + 8) * 20 + cq]      = make_float2(d0[2], d0[3]);
            *(float2*)&pw[r0 * 20 + 8 + cq]        = make_float2(d1[0], d1[1]);
            *(float2*)&pw[(r0 + 8) * 20 + 8 + cq]  = make_float2(d1[2], d1[3]);
        }
    }
    __syncthreads();

    // ---- reduce 4 warp-partials, tanh-clip, mask, store ----
    {
        const int nb = t >> 6;
        const int tt = t & 63;
        const int q  = tt >> 2;
        const int k0 = (tt & 3) * 4;
        const float* pb = (const float*)(nb ? (void*)&sW[0][0][0] : (void*)&sV[0][0][0]);
        const int o = q * 20 + k0;
        const float4 p0v = *(const float4*)&pb[o];
        const float4 p1v = *(const float4*)&pb[320 + o];
        const float4 p2v = *(const float4*)&pb[640 + o];
        const float4 p3v = *(const float4*)&pb[960 + o];
        const float sx = p0v.x + p1v.x + p2v.x + p3v.x;
        const float sy = p0v.y + p1v.y + p2v.y + p3v.y;
        const float sz = p0v.z + p1v.z + p2v.z + p3v.z;
        const float sw2 = p0v.w + p1v.w + p2v.w + p3v.w;
        const unsigned mq = s_mask[nb][q];
        float4 r;
        r.x = ((mq >> (k0 + 0)) & 1u) ? NEGV : 10.f * tanh_fast(sx);
        r.y = ((mq >> (k0 + 1)) & 1u) ? NEGV : 10.f * tanh_fast(sy);
        r.z = ((mq >> (k0 + 2)) & 1u) ? NEGV : 10.f * tanh_fast(sz);
        r.w = ((mq >> (k0 + 3)) & 1u) ? NEGV : 10.f * tanh_fast(sw2);
        *(float4*)&out[(size_t)(b0 + nb) * (AA * AA) + q * AA + k0] = r;
    }
}

extern "C" void kernel_launch(void* const* d_in, const int* in_sizes, int n_in,
                              void* d_out, int out_size) {
    const float* agent_embed = (const float*)d_in[0];
    const float* city_embed  = (const float*)d_in[1];
    const int*   acts        = (const int*)d_in[2];
    const float* Wq    = (const float*)d_in[3];
    const float* Wk    = (const float*)d_in[4];
    const float* Wv    = (const float*)d_in[5];
    const float* Wo    = (const float*)d_in[6];
    const float* ln1_g = (const float*)d_in[7];
    const float* ln1_b = (const float*)d_in[8];
    const float* W1    = (const float*)d_in[9];
    const float* b1v   = (const float*)d_in[10];
    const float* W2    = (const float*)d_in[11];
    const float* b2v   = (const float*)d_in[12];
    const float* ln2_g = (const float*)d_in[13];
    const float* ln2_b = (const float*)d_in[14];
    const float* Wqs   = (const float*)d_in[15];
    const float* Wks   = (const float*)d_in[16];

    const int B = in_sizes[0] / (AA * EE);

    pack_weights_kernel<<<128, 128>>>(Wq, Wk, Wv, Wo, W1, W2, Wqs, Wks);
    conflict_model_kernel<<<B / NB, 128>>>(
        agent_embed, city_embed, acts,
        ln1_g, ln1_b, b1v, b2v, ln2_g, ln2_b,
        (float*)d_out);
}

// round 15
// speedup vs baseline: 1.0680x; 1.0005x over previous
#include <cuda_runtime.h>
#include <cuda_fp16.h>

#define AA 16      // agents
#define EE 128     // embed dim
#define EPH 136    // f16 elems per smem row (272B, staggered for ldmatrix)
#define EPB 272    // row bytes
#define NB 2       // batches per CTA
#define NEGV (-1e9f)

// Packed f16 weights: [m 8][nt 16][kk2 4][lane 32] uint4.
__device__ uint4 g_wpack[8 * 16 * 4 * 32];

__device__ __forceinline__ unsigned pk2h(float lo, float hi) {
    unsigned r;
    asm("cvt.rn.f16x2.f32 %0, %1, %2;" : "=r"(r) : "f"(hi), "f"(lo));
    return r;
}
__device__ __forceinline__ float2 up2h(unsigned u) {
    const __half2 h = *reinterpret_cast<const __half2*>(&u);
    return __half22float2(h);
}
__device__ __forceinline__ unsigned hadd2u(unsigned a, unsigned b) {
    unsigned r;
    asm("add.f16x2 %0, %1, %2;" : "=r"(r) : "r"(a), "r"(b));
    return r;
}
__device__ __forceinline__ unsigned hmax2u(unsigned a, unsigned b) {
    unsigned r;
    asm("max.f16x2 %0, %1, %2;" : "=r"(r) : "r"(a), "r"(b));
    return r;
}
__device__ __forceinline__ float tanh_fast(float x) {
    float r;
    asm("tanh.approx.f32 %0, %1;" : "=f"(r) : "f"(x));
    return r;
}
__device__ __forceinline__ unsigned scvt(const void* p) {
    return (unsigned)__cvta_generic_to_shared(p);
}
__device__ __forceinline__ void ldsm4(unsigned& r0, unsigned& r1, unsigned& r2, unsigned& r3,
                                      unsigned a) {
    asm volatile("ldmatrix.sync.aligned.m8n8.x4.shared.b16 {%0,%1,%2,%3}, [%4];"
                 : "=r"(r0), "=r"(r1), "=r"(r2), "=r"(r3) : "r"(a));
}
__device__ __forceinline__ void ldsm4t(unsigned& r0, unsigned& r1, unsigned& r2, unsigned& r3,
                                       unsigned a) {
    asm volatile("ldmatrix.sync.aligned.m8n8.x4.trans.shared.b16 {%0,%1,%2,%3}, [%4];"
                 : "=r"(r0), "=r"(r1), "=r"(r2), "=r"(r3) : "r"(a));
}
// f16 in, f16 acc — D/C are 2 packed regs already in store layout
__device__ __forceinline__ void mmah(unsigned d[2], unsigned a0, unsigned a1, unsigned a2,
                                     unsigned a3, unsigned b0, unsigned b1) {
    asm("mma.sync.aligned.m16n8k16.row.col.f16.f16.f16.f16 "
        "{%0,%1}, {%2,%3,%4,%5}, {%6,%7}, {%0,%1};"
        : "+r"(d[0]), "+r"(d[1])
        : "r"(a0), "r"(a1), "r"(a2), "r"(a3), "r"(b0), "r"(b1));
}
// f16 in, f32 acc (attention + logits)
__device__ __forceinline__ void mmaf(float d[4], unsigned a0, unsigned a1, unsigned a2,
                                     unsigned a3, unsigned b0, unsigned b1) {
    asm("mma.sync.aligned.m16n8k16.row.col.f32.f16.f16.f32 "
        "{%0,%1,%2,%3}, {%4,%5,%6,%7}, {%8,%9}, {%0,%1,%2,%3};"
        : "+f"(d[0]), "+f"(d[1]), "+f"(d[2]), "+f"(d[3])
        : "r"(a0), "r"(a1), "r"(a2), "r"(a3), "r"(b0), "r"(b1));
}

// ---- prepass: repack 8 fp32 [128][128] weights into f16 uint4 fragment order ----
__global__ void __launch_bounds__(128) pack_weights_kernel(
    const float* __restrict__ Wq, const float* __restrict__ Wk,
    const float* __restrict__ Wv, const float* __restrict__ Wo,
    const float* __restrict__ W1, const float* __restrict__ W2,
    const float* __restrict__ Wqs, const float* __restrict__ Wks)
{
    const int idx = blockIdx.x * blockDim.x + threadIdx.x;   // 0..16383
    const int l  = idx & 31;
    const int k2 = (idx >> 5) & 3;
    const int nt = (idx >> 7) & 15;
    const int m  = idx >> 11;
    const float* W; float sc = 1.f;
    switch (m) {
        case 0: W = Wq; sc = 0.25f; break;                    // fold 1/sqrt(dh)
        case 1: W = Wk; break;
        case 2: W = Wv; break;
        case 3: W = Wo; break;
        case 4: W = W1; break;
        case 5: W = W2; break;
        case 6: W = Wqs; sc = 0.08838834764831845f; break;    // fold 1/sqrt(E)
        default: W = Wks; break;
    }
    const int n  = nt * 8 + (l >> 2);
    const int kb = k2 * 32 + 2 * (l & 3);
    uint4 o;
    o.x = pk2h(W[(kb +  0) * EE + n] * sc, W[(kb +  1) * EE + n] * sc);
    o.y = pk2h(W[(kb +  8) * EE + n] * sc, W[(kb +  9) * EE + n] * sc);
    o.z = pk2h(W[(kb + 16) * EE + n] * sc, W[(kb + 17) * EE + n] * sc);
    o.w = pk2h(W[(kb + 24) * EE + n] * sc, W[(kb + 25) * EE + n] * sc);
    g_wpack[idx] = o;
}

enum { MRAW = 0, MRES = 1, MBRELU = 2, MBRES = 3 };

// acc[nb][nt][2] = X[nb] @ W for this warp's 32 cols. If PRE, k2=0 weight
// fragments come pre-loaded (hoisted above the preceding barrier).
template<bool PRE>
__device__ __forceinline__ void mm_acc(
    const __half (*Xs)[AA][EPH], const uint4* __restrict__ Wp,
    int w, int l, unsigned offA, unsigned acc[NB][4][2], const uint4* pre)
{
#pragma unroll
    for (int nb = 0; nb < NB; nb++)
#pragma unroll
        for (int nt = 0; nt < 4; nt++) { acc[nb][nt][0] = 0u; acc[nb][nt][1] = 0u; }
    const unsigned xb0 = scvt(&Xs[0][0][0]) + offA;
    const unsigned xb1 = scvt(&Xs[1][0][0]) + offA;
#pragma unroll
    for (int k2 = 0; k2 < 4; k2++) {
        uint4 wfr[4];
        if (PRE && k2 == 0) {
#pragma unroll
            for (int nt = 0; nt < 4; nt++) wfr[nt] = pre[nt];
        } else {
#pragma unroll
            for (int nt = 0; nt < 4; nt++)
                wfr[nt] = __ldg(&Wp[(((w * 4 + nt) * 4) + k2) * 32 + l]);
        }
#pragma unroll
        for (int nb = 0; nb < NB; nb++) {
            const unsigned xb = nb ? xb1 : xb0;
            unsigned a0, a1, a2, a3, c0, c1, c2, c3;
            ldsm4(a0, a1, a2, a3, xb + (2 * k2) * 32);
            ldsm4(c0, c1, c2, c3, xb + (2 * k2 + 1) * 32);
#pragma unroll
            for (int nt = 0; nt < 4; nt++) {
                mmah(acc[nb][nt], a0, a1, a2, a3, wfr[nt].x, wfr[nt].y);
                mmah(acc[nb][nt], c0, c1, c2, c3, wfr[nt].z, wfr[nt].w);
            }
        }
    }
}

// Full GEMM phase with packed-f16 smem epilogue.
template<int MODE, bool PRE>
__device__ __forceinline__ void mm_phase(
    const __half (*Xs)[AA][EPH], __half (*Ys)[AA][EPH],
    const __half (*Rs)[AA][EPH], const float* __restrict__ bias,
    const uint4* __restrict__ Wp, int w, int l, unsigned offA, int r0, int cq,
    const uint4* pre = nullptr)
{
    unsigned acc[NB][4][2];
    mm_acc<PRE>(Xs, Wp, w, l, offA, acc, pre);
#pragma unroll
    for (int nb = 0; nb < NB; nb++) {
        char* yb = (char*)&Ys[nb][0][0];
        const char* rb = (MODE == MRES || MODE == MBRES) ? (const char*)&Rs[nb][0][0] : nullptr;
#pragma unroll
        for (int nt = 0; nt < 4; nt++) {
            const int colb = (w * 4 + nt) * 8 + cq;
            const unsigned off0 = r0 * EPB + colb * 2;
            const unsigned off1 = off0 + 8 * EPB;
            unsigned y0 = acc[nb][nt][0], y1 = acc[nb][nt][1];
            if (MODE == MRES) {
                y0 = hadd2u(y0, *(const unsigned*)(rb + off0));
                y1 = hadd2u(y1, *(const unsigned*)(rb + off1));
            } else if (MODE == MBRELU) {
                const float2 bv = *reinterpret_cast<const float2*>(&bias[colb]);
                const unsigned bh = pk2h(bv.x, bv.y);
                y0 = hmax2u(hadd2u(y0, bh), 0u);
                y1 = hmax2u(hadd2u(y1, bh), 0u);
            } else if (MODE == MBRES) {
                const float2 bv = *reinterpret_cast<const float2*>(&bias[colb]);
                const unsigned bh = pk2h(bv.x, bv.y);
                y0 = hadd2u(hadd2u(y0, bh), *(const unsigned*)(rb + off0));
                y1 = hadd2u(hadd2u(y1, bh), *(const unsigned*)(rb + off1));
            }
            *(unsigned*)(yb + off0) = y0;
            *(unsigned*)(yb + off1) = y1;
        }
    }
}

// Wide in-place LN: 16 lanes x uint4 per row, 2 rows/iter, stats fp32.
__device__ __forceinline__ void ln_phase(__half (*X)[EPH], const float* __restrict__ g,
                                         const float* __restrict__ bsh, int hv, int l)
{
    const int sub = l >> 4;     // row selector within pair
    const int cl  = l & 15;     // 8-col group
    const float4 gA = __ldg((const float4*)&g[cl * 8]);
    const float4 gB = __ldg((const float4*)&g[cl * 8 + 4]);
    const float4 bA = __ldg((const float4*)&bsh[cl * 8]);
    const float4 bB = __ldg((const float4*)&bsh[cl * 8 + 4]);
#pragma unroll
    for (int rr = 0; rr < 4; rr++) {
        const int r = hv * 8 + rr * 2 + sub;
        char* rp = (char*)&X[r][0] + cl * 16;
        const uint4 p = *(const uint4*)rp;
        const float2 v0 = up2h(p.x), v1 = up2h(p.y), v2 = up2h(p.z), v3 = up2h(p.w);
        float s  = (v0.x + v0.y) + (v1.x + v1.y) + (v2.x + v2.y) + (v3.x + v3.y);
        float ss = fmaf(v0.x, v0.x, fmaf(v0.y, v0.y,
                   fmaf(v1.x, v1.x, fmaf(v1.y, v1.y,
                   fmaf(v2.x, v2.x, fmaf(v2.y, v2.y,
                   fmaf(v3.x, v3.x, v3.y * v3.y)))))));
#pragma unroll
        for (int o = 8; o > 0; o >>= 1) {   // reduce over the 16-lane row group
            s  += __shfl_xor_sync(0xffffffffu, s, o);
            ss += __shfl_xor_sync(0xffffffffu, ss, o);
        }
        const float mu  = s * (1.f / 128.f);
        const float var = ss * (1.f / 128.f) - mu * mu;
        const float inv = rsqrtf(var + 1e-5f);
        uint4 q;
        q.x = pk2h((v0.x - mu) * inv * gA.x + bA.x, (v0.y - mu) * inv * gA.y + bA.y);
        q.y = pk2h((v1.x - mu) * inv * gA.z + bA.z, (v1.y - mu) * inv * gA.w + bA.w);
        q.z = pk2h((v2.x - mu) * inv * gB.x + bB.x, (v2.y - mu) * inv * gB.y + bB.y);
        q.w = pk2h((v3.x - mu) * inv * gB.z + bB.z, (v3.y - mu) * inv * gB.w + bB.w);
        *(uint4*)rp = q;
    }
}

// Prefetch this warp's k2=0 weight fragments for a phase (issued before a barrier).
__device__ __forceinline__ void wpre_load(uint4 pre[4], const uint4* __restrict__ Wp,
                                          int w, int l) {
#pragma unroll
    for (int nt = 0; nt < 4; nt++)
        pre[nt] = __ldg(&Wp[((w * 4 + nt) * 4) * 32 + l]);
}

__global__ void __launch_bounds__(128, 6)
conflict_model_kernel(
    const float* __restrict__ agent_embed,  // [B,16,128]
    const float* __restrict__ city_embed,   // [B,128,128]
    const int*   __restrict__ acts,         // [B,16]
    const float* __restrict__ ln1_g, const float* __restrict__ ln1_b,
    const float* __restrict__ b1v,  const float* __restrict__ b2v,
    const float* __restrict__ ln2_g, const float* __restrict__ ln2_b,
    float* __restrict__ out)                // [B,16,16]
{
    __shared__ __align__(16) __half sA[NB][AA][EPH];   // agent (ks source)
    __shared__ __align__(16) __half sX[NB][AA][EPH];   // selected -> cac2 (LN2)
    __shared__ __align__(16) __half sV[NB][AA][EPH];   // v -> h -> logit partials nb0
    __shared__ __align__(16) __half sW[NB][AA][EPH];   // attnO -> ffn hid -> partials nb1
    __shared__ int      s_acts[NB][AA];
    __shared__ unsigned s_mask[NB][AA];

    const int t = threadIdx.x;
    const int w = t >> 5, l = t & 31;
    const int hv = w & 1, nbw = w >> 1;
    const int r0 = l >> 2, cq = 2 * (l & 3);
    const int b0 = blockIdx.x * NB;

    const unsigned offA = (unsigned)(((l & 7) + ((l >> 3) & 1) * 8) * EPB + ((l >> 4) & 1) * 16);

    uint4 pre[4];

    // ---- acts + mask (warps 0,2) & agent rows (all warps) ----
    if (hv == 0) {
        int av = (l < AA) ? acts[(b0 + nbw) * AA + l] : 0;
        unsigned m = 0;
#pragma unroll
        for (int j = 0; j < AA; j++) {
            const int aj = __shfl_sync(0xffffffffu, av, j);
            const bool conflict = (av == 0) ? (j == l) : (aj == av);
            if (!conflict) m |= (1u << j);
        }
        if (l < AA) { s_acts[nbw][l] = av; s_mask[nbw][l] = m; }
    }
#pragma unroll
    for (int rr = 0; rr < 8; rr++) {
        const int r = hv * 8 + rr;
        const float4 v = *reinterpret_cast<const float4*>(
            agent_embed + ((size_t)(b0 + nbw) * AA + r) * EE + 4 * l);
        uint2 p; p.x = pk2h(v.x, v.y); p.y = pk2h(v.z, v.w);
        *(uint2*)((char*)&sA[nbw][r][0] + 8 * l) = p;
    }
    __syncthreads();
#pragma unroll
    for (int rr = 0; rr < 8; rr++) {
        const int r = hv * 8 + rr;
        const int ci = s_acts[nbw][r];
        const float4 v = *reinterpret_cast<const float4*>(
            city_embed + ((size_t)(b0 + nbw) * 128 + ci) * EE + 4 * l);
        uint2 p; p.x = pk2h(v.x, v.y); p.y = pk2h(v.z, v.w);
        *(uint2*)((char*)&sX[nbw][r][0] + 8 * l) = p;
    }
    wpre_load(pre, g_wpack + 2 * 2048, w, l);   // prefetch Wv k2=0
    __syncthreads();

    // ---- v -> smem ; k, q -> packed register fragments ----
    mm_phase<MRAW, true>(sA, sV, nullptr, nullptr, g_wpack + 2 * 2048, w, l, offA, r0, cq, pre);
    unsigned kp[NB][4][2], qp[NB][4][2];
    mm_acc<false>(sA, g_wpack + 1 * 2048, w, l, offA, kp, nullptr);
    mm_acc<false>(sX, g_wpack + 0 * 2048, w, l, offA, qp, nullptr);  // Wq pre-scaled
    __syncwarp();  // V tile (cols 32w) is warp-private

    // ---- attention: warp w handles heads 2w, 2w+1 for BOTH batches ----
#pragma unroll
    for (int nb = 0; nb < NB; nb++) {
        const unsigned vb = scvt(&sV[nb][0][0]);
        const unsigned m0 = s_mask[nb][r0], m1 = s_mask[nb][r0 + 8];
#pragma unroll
        for (int hh = 0; hh < 2; hh++) {
            const int h = 2 * w + hh;
            const unsigned cb = 32u * h;
            const unsigned a0 = qp[nb][2 * hh][0], a1 = qp[nb][2 * hh][1];
            const unsigned a2 = qp[nb][2 * hh + 1][0], a3 = qp[nb][2 * hh + 1][1];
            float s0[4] = {0, 0, 0, 0}, s1[4] = {0, 0, 0, 0};
            mmaf(s0, a0, a1, a2, a3, kp[nb][2 * hh][0], kp[nb][2 * hh + 1][0]);
            mmaf(s1, a0, a1, a2, a3, kp[nb][2 * hh][1], kp[nb][2 * hh + 1][1]);
            if ((m0 >> cq) & 1)       s0[0] = NEGV;
            if ((m0 >> (cq + 1)) & 1) s0[1] = NEGV;
            if ((m1 >> cq) & 1)       s0[2] = NEGV;
            if ((m1 >> (cq + 1)) & 1) s0[3] = NEGV;
            if ((m0 >> (cq + 8)) & 1) s1[0] = NEGV;
            if ((m0 >> (cq + 9)) & 1) s1[1] = NEGV;
            if ((m1 >> (cq + 8)) & 1) s1[2] = NEGV;
            if ((m1 >> (cq + 9)) & 1) s1[3] = NEGV;
            float mx0 = fmaxf(fmaxf(s0[0], s0[1]), fmaxf(s1[0], s1[1]));
            float mx1 = fmaxf(fmaxf(s0[2], s0[3]), fmaxf(s1[2], s1[3]));
            mx0 = fmaxf(mx0, __shfl_xor_sync(0xffffffffu, mx0, 1));
            mx0 = fmaxf(mx0, __shfl_xor_sync(0xffffffffu, mx0, 2));
            mx1 = fmaxf(mx1, __shfl_xor_sync(0xffffffffu, mx1, 1));
            mx1 = fmaxf(mx1, __shfl_xor_sync(0xffffffffu, mx1, 2));
            s0[0] = __expf(s0[0] - mx0); s0[1] = __expf(s0[1] - mx0);
            s1[0] = __expf(s1[0] - mx0); s1[1] = __expf(s1[1] - mx0);
            s0[2] = __expf(s0[2] - mx1); s0[3] = __expf(s0[3] - mx1);
            s1[2] = __expf(s1[2] - mx1); s1[3] = __expf(s1[3] - mx1);
            float sm0 = s0[0] + s0[1] + s1[0] + s1[1];
            float sm1 = s0[2] + s0[3] + s1[2] + s1[3];
            sm0 += __shfl_xor_sync(0xffffffffu, sm0, 1);
            sm0 += __shfl_xor_sync(0xffffffffu, sm0, 2);
            sm1 += __shfl_xor_sync(0xffffffffu, sm1, 1);
            sm1 += __shfl_xor_sync(0xffffffffu, sm1, 2);
            const float inv0 = 1.f / sm0, inv1 = 1.f / sm1;
            const unsigned p0 = pk2h(s0[0], s0[1]);
            const unsigned p1 = pk2h(s0[2], s0[3]);
            const unsigned p2 = pk2h(s1[0], s1[1]);
            const unsigned p3 = pk2h(s1[2], s1[3]);
            unsigned v0, v1, v2, v3;
            ldsm4t(v0, v1, v2, v3, vb + offA + cb);
            float o0[4] = {0, 0, 0, 0}, o1[4] = {0, 0, 0, 0};
            mmaf(o0, p0, p1, p2, p3, v0, v1);
            mmaf(o1, p0, p1, p2, p3, v2, v3);
            char* yb = (char*)&sW[nb][0][0];
            const unsigned c0 = r0 * EPB + (16 * h + cq) * 2;
            const unsigned c1 = c0 + 8 * EPB;
            *(unsigned*)(yb + c0)      = pk2h(o0[0] * inv0, o0[1] * inv0);
            *(unsigned*)(yb + c1)      = pk2h(o0[2] * inv1, o0[3] * inv1);
            *(unsigned*)(yb + c0 + 16) = pk2h(o1[0] * inv0, o1[1] * inv0);
            *(unsigned*)(yb + c1 + 16) = pk2h(o1[2] * inv1, o1[3] * inv1);
        }
    }
    wpre_load(pre, g_wpack + 3 * 2048, w, l);   // prefetch Wo k2=0
    __syncthreads();

    // ---- attnO @ Wo + selected -> sV (v dead); LN1 ----
    mm_phase<MRES, true>(sW, sV, sX, nullptr, g_wpack + 3 * 2048, w, l, offA, r0, cq, pre);
    __syncthreads();
    ln_phase(sV[nbw], ln1_g, ln1_b, hv, l);
    wpre_load(pre, g_wpack + 4 * 2048, w, l);   // prefetch W1 k2=0
    __syncthreads();

    // ---- FFN hidden = relu(h @ W1 + b1) -> sW (attnO dead) ----
    mm_phase<MBRELU, true>(sV, sW, nullptr, b1v, g_wpack + 4 * 2048, w, l, offA, r0, cq, pre);
    wpre_load(pre, g_wpack + 5 * 2048, w, l);   // prefetch W2 k2=0
    __syncthreads();

    // ---- FFN out + b2 + h -> sX (selected dead); LN2 ----
    mm_phase<MBRES, true>(sW, sX, sV, b2v, g_wpack + 5 * 2048, w, l, offA, r0, cq, pre);
    __syncthreads();
    ln_phase(sX[nbw], ln2_g, ln2_b, hv, l);
    wpre_load(pre, g_wpack + 6 * 2048, w, l);   // prefetch Wq_s k2=0
    __syncthreads();

    // ---- qs, ks -> register fragments; per-warp partial logits over 32-col slice ----
    {
        unsigned qs2[NB][4][2], ks2[NB][4][2];
        mm_acc<true>(sX, g_wpack + 6 * 2048, w, l, offA, qs2, pre);  // pre-scaled
        mm_acc<false>(sA, g_wpack + 7 * 2048, w, l, offA, ks2, nullptr);
#pragma unroll
        for (int nb = 0; nb < NB; nb++) {
            float d0[4] = {0, 0, 0, 0}, d1[4] = {0, 0, 0, 0};
#pragma unroll
            for (int j = 0; j < 2; j++) {
                const unsigned a0 = qs2[nb][2 * j][0], a1 = qs2[nb][2 * j][1];
                const unsigned a2 = qs2[nb][2 * j + 1][0], a3 = qs2[nb][2 * j + 1][1];
                mmaf(d0, a0, a1, a2, a3, ks2[nb][2 * j][0], ks2[nb][2 * j + 1][0]);
                mmaf(d1, a0, a1, a2, a3, ks2[nb][2 * j][1], ks2[nb][2 * j + 1][1]);
            }
            float* pw = (float*)(nb ? (void*)&sW[0][0][0] : (void*)&sV[0][0][0]) + w * 320;
            *(float2*)&pw[r0 * 20 + cq]            = make_float2(d0[0], d0[1]);
            *(float2*)&pw[(r0 + 8) * 20 + cq]      = make_float2(d0[2], d0[3]);
            *(float2*)&pw[r0 * 20 + 8 + cq]        = make_float2(d1[0], d1[1]);
            *(float2*)&pw[(r0 + 8) * 20 + 8 + cq]  = make_float2(d1[2], d1[3]);
        }
    }
    __syncthreads();

    // ---- reduce 4 warp-partials, tanh-clip, mask, store ----
    {
        const int nb = t >> 6;
        const int tt = t & 63;
        const int q  = tt >> 2;
        const int k0 = (tt & 3) * 4;
        const float* pb = (const float*)(nb ? (void*)&sW[0][0][0] : (void*)&sV[0][0][0]);
        const int o = q * 20 + k0;
        const float4 p0v = *(const float4*)&pb[o];
        const float4 p1v = *(const float4*)&pb[320 + o];
        const float4 p2v = *(const float4*)&pb[640 + o];
        const float4 p3v = *(const float4*)&pb[960 + o];
        const float sx = p0v.x + p1v.x + p2v.x + p3v.x;
        const float sy = p0v.y + p1v.y + p2v.y + p3v.y;
        const float sz = p0v.z + p1v.z + p2v.z + p3v.z;
        const float sw2 = p0v.w + p1v.w + p2v.w + p3v.w;
        const unsigned mq = s_mask[nb][q];
        float4 r;
        r.x = ((mq >> (k0 + 0)) & 1u) ? NEGV : 10.f * tanh_fast(sx);
        r.y = ((mq >> (k0 + 1)) & 1u) ? NEGV : 10.f * tanh_fast(sy);
        r.z = ((mq >> (k0 + 2)) & 1u) ? NEGV : 10.f * tanh_fast(sz);
        r.w = ((mq >> (k0 + 3)) & 1u) ? NEGV : 10.f * tanh_fast(sw2);
        *(float4*)&out[(size_t)(b0 + nb) * (AA * AA) + q * AA + k0] = r;
    }
}

extern "C" void kernel_launch(void* const* d_in, const int* in_sizes, int n_in,
                              void* d_out, int out_size) {
    const float* agent_embed = (const float*)d_in[0];
    const float* city_embed  = (const float*)d_in[1];
    const int*   acts        = (const int*)d_in[2];
    const float* Wq    = (const float*)d_in[3];
    const float* Wk    = (const float*)d_in[4];
    const float* Wv    = (const float*)d_in[5];
    const float* Wo    = (const float*)d_in[6];
    const float* ln1_g = (const float*)d_in[7];
    const float* ln1_b = (const float*)d_in[8];
    const float* W1    = (const float*)d_in[9];
    const float* b1v   = (const float*)d_in[10];
    const float* W2    = (const float*)d_in[11];
    const float* b2v   = (const float*)d_in[12];
    const float* ln2_g = (const float*)d_in[13];
    const float* ln2_b = (const float*)d_in[14];
    const float* Wqs   = (const float*)d_in[15];
    const float* Wks   = (const float*)d_in[16];

    const int B = in_sizes[0] / (AA * EE);

    pack_weights_kernel<<<128, 128>>>(Wq, Wk, Wv, Wo, W1, W2, Wqs, Wks);
    conflict_model_kernel<<<B / NB, 128>>>(
        agent_embed, city_embed, acts,
        ln1_g, ln1_b, b1v, b2v, ln2_g, ln2_b,
        (float*)d_out);
}